// round 7
// baseline (speedup 1.0000x reference)
#include <cuda_runtime.h>

// Problem constants
#define N_   8
#define C_   256
#define H_   128
#define W_   128
#define HW_  16384
#define NB_  20
#define TEMP 0.5f
#define IMGW 800.0f
#define IMGH 800.0f

#define K1_CHUNKS 64                 // hw chunks per image in K1
#define K1_BLOCKS (N_ * K1_CHUNKS)   // 512
#define K6_BLOCKS 1024

// Scratch (no allocation allowed -> __device__ globals)
__device__ float g_rowsum[N_ * HW_];          // sum_c |T|, indexed [n*HW + hw]
__device__ float g_colpart[K1_BLOCKS * C_];   // per-block partial channel sums
__device__ float g_sqC[N_ * C_];              // sqrt(C_att)
__device__ float g_smax[N_];                  // max spatial logit per image
__device__ float g_A[N_];                     // sqrt(HW / ssum) per image
__device__ float g_sqbg[N_];                  // sqrt(1/bg_count) per image
__device__ float g_fg[N_ * HW_];              // fg mask, [n*HW + hw]
__device__ float g_part[K6_BLOCKS];           // main-pass block partials
__device__ unsigned int g_cnt = 0;            // last-block counter (self-resetting)

// ---------------------------------------------------------------------------
// K1: one pass over preds_T. Row sums of |T| + partial channel sums.
// Grid: (K1_CHUNKS, N_), 256 threads (8 warps). Warp handles rows strided by 8.
// ---------------------------------------------------------------------------
__global__ void __launch_bounds__(256) k1_stats(const float* __restrict__ T) {
    const int n = blockIdx.y;
    const int chunk = blockIdx.x;
    const int w = threadIdx.x >> 5;
    const int l = threadIdx.x & 31;

    __shared__ float scol[8][C_];

    float col[8];
#pragma unroll
    for (int j = 0; j < 8; j++) col[j] = 0.0f;

    const int hw0 = chunk * (HW_ / K1_CHUNKS);   // 256 rows per block
#pragma unroll 4
    for (int i = 0; i < 32; i++) {
        const int hw = hw0 + w + 8 * i;
        const float4* p = reinterpret_cast<const float4*>(T + (size_t)(hw * N_ + n) * C_);
        float4 a = p[l];        // c = 4l .. 4l+3
        float4 b = p[32 + l];   // c = 128+4l ..
        float a0 = fabsf(a.x), a1 = fabsf(a.y), a2 = fabsf(a.z), a3 = fabsf(a.w);
        float b0 = fabsf(b.x), b1 = fabsf(b.y), b2 = fabsf(b.z), b3 = fabsf(b.w);
        col[0] += a0; col[1] += a1; col[2] += a2; col[3] += a3;
        col[4] += b0; col[5] += b1; col[6] += b2; col[7] += b3;
        float rs = (a0 + a1) + (a2 + a3) + (b0 + b1) + (b2 + b3);
#pragma unroll
        for (int off = 16; off; off >>= 1)
            rs += __shfl_xor_sync(0xffffffffu, rs, off);
        if (l == 0) g_rowsum[n * HW_ + hw] = rs;
    }

#pragma unroll
    for (int j = 0; j < 4; j++) {
        scol[w][4 * l + j]       = col[j];
        scol[w][128 + 4 * l + j] = col[4 + j];
    }
    __syncthreads();

    const int t = threadIdx.x;  // 256 threads == C_
    float p = 0.0f;
#pragma unroll
    for (int ww = 0; ww < 8; ww++) p += scol[ww][t];
    g_colpart[(n * K1_CHUNKS + chunk) * C_ + t] = p;
}

// ---------------------------------------------------------------------------
// KMETA: fused per-image metadata. Grid: N_ blocks, 256 threads.
// Phase A: channel softmax -> g_sqC.
// Phase B: spatial softmax stats -> g_smax, g_A.
// Phase C: box masks -> g_fg, g_sqbg.
// ---------------------------------------------------------------------------
__global__ void __launch_bounds__(256) kmeta(const float* __restrict__ gt) {
    const int n = blockIdx.x;
    const int t = threadIdx.x;
    __shared__ float sh[256];

    // ---- Phase A: channel softmax (t == channel index) ----
    float v = 0.0f;
    for (int k = 0; k < K1_CHUNKS; k++)
        v += g_colpart[(n * K1_CHUNKS + k) * C_ + t];
    const float logit = (v / (float)HW_) / TEMP;

    sh[t] = logit;
    __syncthreads();
    for (int s = 128; s; s >>= 1) {
        if (t < s) sh[t] = fmaxf(sh[t], sh[t + s]);
        __syncthreads();
    }
    const float cmx = sh[0];
    __syncthreads();
    const float e = expf(logit - cmx);
    sh[t] = e;
    __syncthreads();
    for (int s = 128; s; s >>= 1) {
        if (t < s) sh[t] += sh[t + s];
        __syncthreads();
    }
    const float csum = sh[0];
    __syncthreads();
    g_sqC[n * C_ + t] = sqrtf((float)C_ * e / csum);

    // ---- Phase B: spatial stats ----
    const float invCT = 1.0f / ((float)C_ * TEMP);
    const float4* rp = reinterpret_cast<const float4*>(g_rowsum + n * HW_);
    float mrs = -1e30f;
    for (int i = t; i < HW_ / 4; i += 256) {
        float4 a = rp[i];
        mrs = fmaxf(mrs, fmaxf(fmaxf(a.x, a.y), fmaxf(a.z, a.w)));
    }
    sh[t] = mrs;
    __syncthreads();
    for (int s = 128; s; s >>= 1) {
        if (t < s) sh[t] = fmaxf(sh[t], sh[t + s]);
        __syncthreads();
    }
    const float lmax = sh[0] * invCT;
    __syncthreads();

    float se = 0.0f;
    for (int i = t; i < HW_ / 4; i += 256) {
        float4 a = rp[i];
        se += expf(a.x * invCT - lmax) + expf(a.y * invCT - lmax)
            + expf(a.z * invCT - lmax) + expf(a.w * invCT - lmax);
    }
    sh[t] = se;
    __syncthreads();
    for (int s = 128; s; s >>= 1) {
        if (t < s) sh[t] += sh[t + s];
        __syncthreads();
    }
    if (t == 0) {
        g_smax[n] = lmax;
        g_A[n]    = sqrtf((float)HW_ / sh[0]);
    }
    __syncthreads();

    // ---- Phase C: masks ----
    __shared__ int   shmin[NB_], shmax[NB_], swmin[NB_], swmax[NB_];
    __shared__ float sarea[NB_];
    if (t < NB_) {
        const float* b = gt + (size_t)(n * NB_ + t) * 4;
        int wmin = (int)floorf(b[0] / IMGW * (float)W_);
        int wmax = (int)ceilf (b[2] / IMGW * (float)W_);
        int hmin = (int)floorf(b[1] / IMGH * (float)H_);
        int hmax = (int)ceilf (b[3] / IMGH * (float)H_);
        swmin[t] = wmin; swmax[t] = wmax; shmin[t] = hmin; shmax[t] = hmax;
        sarea[t] = 1.0f / (float)(hmax + 1 - hmin) / (float)(wmax + 1 - wmin);
    }
    __syncthreads();

    int cnt = 0;
    for (int i = t; i < HW_; i += 256) {
        const int hh = i >> 7;        // / W_
        const int ww = i & (W_ - 1);
        float fg = 0.0f;
#pragma unroll
        for (int b = 0; b < NB_; b++) {
            bool inside = (hh >= shmin[b]) & (hh <= shmax[b]) &
                          (ww >= swmin[b]) & (ww <= swmax[b]);
            if (inside) fg = fmaxf(fg, sarea[b]);
        }
        g_fg[n * HW_ + i] = fg;
        if (fg <= 0.0f) cnt++;
    }
    __shared__ int shi[256];
    shi[t] = cnt;
    __syncthreads();
    for (int s = 128; s; s >>= 1) {
        if (t < s) shi[t] += shi[t + s];
        __syncthreads();
    }
    if (t == 0) {
        int c = shi[0];
        g_sqbg[n] = sqrtf(1.0f / (float)(c > 0 ? c : 1));
    }
}

// ---------------------------------------------------------------------------
// K6: main pass over S and T, weight computed inline, per-lane deferred
// reduction, last block finishes the scalar. Grid: K6_BLOCKS, 256 thr.
// ---------------------------------------------------------------------------
__global__ void __launch_bounds__(256) k6_main(const float* __restrict__ S,
                                              const float* __restrict__ T,
                                              float* __restrict__ out) {
    __shared__ float sqc[N_ * C_];
    __shared__ float sA[N_], sMx[N_], sBg[N_];
    for (int i = threadIdx.x; i < N_ * C_; i += 256) sqc[i] = g_sqC[i];
    if (threadIdx.x < N_) {
        sA[threadIdx.x]  = g_A[threadIdx.x];
        sMx[threadIdx.x] = g_smax[threadIdx.x];
        sBg[threadIdx.x] = g_sqbg[threadIdx.x];
    }
    __syncthreads();

    const int w = threadIdx.x >> 5;
    const int l = threadIdx.x & 31;
    const int gw = blockIdx.x * 8 + w;
    const int NW = K6_BLOCKS * 8;
    const float invCT2 = 0.5f / ((float)C_ * TEMP);   // half-logit (for sqrt(exp))

    float acc = 0.0f;
#pragma unroll 4
    for (int r = gw; r < N_ * HW_; r += NW) {
        const int n = r & (N_ - 1);
        const int hw = r >> 3;
        const float4* ps = reinterpret_cast<const float4*>(S + (size_t)r * C_);
        const float4* pt = reinterpret_cast<const float4*>(T + (size_t)r * C_);
        float4 a = ps[l],      b = pt[l];
        float4 c = ps[32 + l], d = pt[32 + l];
        const float4* qr = reinterpret_cast<const float4*>(sqc + n * C_);
        float4 qa = qr[l], qb = qr[32 + l];

        float v = fabsf(a.x - b.x) * qa.x + fabsf(a.y - b.y) * qa.y
                + fabsf(a.z - b.z) * qa.z + fabsf(a.w - b.w) * qa.w
                + fabsf(c.x - d.x) * qb.x + fabsf(c.y - d.y) * qb.y
                + fabsf(c.z - d.z) * qb.z + fabsf(c.w - d.w) * qb.w;

        // inline per-row weight: sqrt(S_att) * (sqrt(fg) + sqrt(bg))
        const float rs = g_rowsum[n * HW_ + hw];
        const float fg = g_fg[n * HW_ + hw];
        const float sqrtS = sA[n] * expf(rs * invCT2 - 0.5f * sMx[n]);
        const float wrow  = sqrtS * (sqrtf(fg) + ((fg <= 0.0f) ? sBg[n] : 0.0f));
        acc += v * wrow;             // deferred: no per-row shuffle chain
    }

#pragma unroll
    for (int off = 16; off; off >>= 1)
        acc += __shfl_xor_sync(0xffffffffu, acc, off);

    __shared__ float sp[8];
    if (l == 0) sp[w] = acc;
    __syncthreads();

    __shared__ bool is_last;
    if (threadIdx.x == 0) {
        float s = 0.0f;
#pragma unroll
        for (int i = 0; i < 8; i++) s += sp[i];
        g_part[blockIdx.x] = s;
        __threadfence();
        unsigned int prev = atomicAdd(&g_cnt, 1u);
        is_last = (prev == (unsigned)(K6_BLOCKS - 1));
    }
    __syncthreads();

    if (is_last) {
        // deterministic fixed-order final reduce over g_part
        __shared__ float sh[256];
        const int t = threadIdx.x;
        float s = 0.0f;
        for (int i = t; i < K6_BLOCKS; i += 256) s += g_part[i];
        sh[t] = s;
        __syncthreads();
        for (int st = 128; st; st >>= 1) {
            if (t < st) sh[t] += sh[t + st];
            __syncthreads();
        }
        if (t == 0) {
            out[0] = sh[0] / (float)HW_;   // RATIO == 1
            g_cnt = 0;                     // reset for next graph replay
        }
    }
}

extern "C" void kernel_launch(void* const* d_in, const int* in_sizes, int n_in,
                              void* d_out, int out_size) {
    const float* preds_S = (const float*)d_in[0];
    const float* preds_T = (const float*)d_in[1];
    const float* gt      = (const float*)d_in[2];
    float* out = (float*)d_out;

    k1_stats<<<dim3(K1_CHUNKS, N_), 256>>>(preds_T);
    kmeta<<<N_, 256>>>(gt);
    k6_main<<<K6_BLOCKS, 256>>>(preds_S, preds_T, out);
}

// round 10
// speedup vs baseline: 1.0369x; 1.0369x over previous
#include <cuda_runtime.h>

// Problem constants
#define N_   8
#define C_   256
#define H_   128
#define W_   128
#define HW_  16384
#define NB_  20
#define TEMP 0.5f
#define IMGW 800.0f
#define IMGH 800.0f

#define K1_CHUNKS 128                // hw chunks per image in K1 (128 rows each)
#define K1_BLOCKS (N_ * K1_CHUNKS)   // 1024
#define K6_BLOCKS 1024

// Scratch (no allocation allowed -> __device__ globals)
__device__ float g_rowsum[N_ * HW_];          // sum_c |T|, indexed [n*HW + hw]
__device__ float g_colpart[K1_BLOCKS * C_];   // per-block partial channel sums
__device__ float g_sqC[N_ * C_];              // sqrt(C_att)
__device__ float g_smax[N_];                  // max spatial logit per image
__device__ float g_A[N_];                     // sqrt(HW / ssum) per image
__device__ float g_fg[N_ * HW_];              // fg mask, [n*HW + hw]
__device__ float g_roww[N_ * HW_];            // per-row weight, [n*HW + hw]
__device__ float g_part[K6_BLOCKS];           // main-pass block partials
__device__ unsigned int g_cnt = 0;            // last-block counter (self-resetting)

// ---------------------------------------------------------------------------
// K1: one pass over preds_T. Row sums of |T| + partial channel sums.
// Grid: (K1_CHUNKS, N_) = 1024 blocks, 256 threads (8 warps).
// Each block: 128 rows; each warp: 16 rows strided by 8.
// ---------------------------------------------------------------------------
__global__ void __launch_bounds__(256) k1_stats(const float* __restrict__ T) {
    const int n = blockIdx.y;
    const int chunk = blockIdx.x;
    const int w = threadIdx.x >> 5;
    const int l = threadIdx.x & 31;

    __shared__ float scol[8][C_];

    float col[8];
#pragma unroll
    for (int j = 0; j < 8; j++) col[j] = 0.0f;

    const int hw0 = chunk * (HW_ / K1_CHUNKS);   // 128 rows per block
#pragma unroll 4
    for (int i = 0; i < 16; i++) {
        const int hw = hw0 + w + 8 * i;
        const float4* p = reinterpret_cast<const float4*>(T + (size_t)(hw * N_ + n) * C_);
        float4 a = p[l];        // c = 4l .. 4l+3
        float4 b = p[32 + l];   // c = 128+4l ..
        float a0 = fabsf(a.x), a1 = fabsf(a.y), a2 = fabsf(a.z), a3 = fabsf(a.w);
        float b0 = fabsf(b.x), b1 = fabsf(b.y), b2 = fabsf(b.z), b3 = fabsf(b.w);
        col[0] += a0; col[1] += a1; col[2] += a2; col[3] += a3;
        col[4] += b0; col[5] += b1; col[6] += b2; col[7] += b3;
        float rs = (a0 + a1) + (a2 + a3) + (b0 + b1) + (b2 + b3);
#pragma unroll
        for (int off = 16; off; off >>= 1)
            rs += __shfl_xor_sync(0xffffffffu, rs, off);
        if (l == 0) g_rowsum[n * HW_ + hw] = rs;
    }

#pragma unroll
    for (int j = 0; j < 4; j++) {
        scol[w][4 * l + j]       = col[j];
        scol[w][128 + 4 * l + j] = col[4 + j];
    }
    __syncthreads();

    const int t = threadIdx.x;  // 256 threads == C_
    float p = 0.0f;
#pragma unroll
    for (int ww = 0; ww < 8; ww++) p += scol[ww][t];
    g_colpart[(n * K1_CHUNKS + chunk) * C_ + t] = p;
}

// ---------------------------------------------------------------------------
// KMETA: fused per-image metadata. Grid: N_ blocks, 256 threads.
// Phase A: channel softmax -> g_sqC.
// Phase B: spatial softmax stats.
// Phase C: box masks -> g_fg, bg count.
// Phase D: per-row weight -> g_roww (keeps k6's hot loop branchless).
// ---------------------------------------------------------------------------
__global__ void __launch_bounds__(256) kmeta(const float* __restrict__ gt) {
    const int n = blockIdx.x;
    const int t = threadIdx.x;
    __shared__ float sh[256];

    // ---- Phase A: channel softmax (t == channel index) ----
    float v = 0.0f;
#pragma unroll 8
    for (int k = 0; k < K1_CHUNKS; k++)
        v += g_colpart[(n * K1_CHUNKS + k) * C_ + t];
    const float logit = (v / (float)HW_) / TEMP;

    sh[t] = logit;
    __syncthreads();
    for (int s = 128; s; s >>= 1) {
        if (t < s) sh[t] = fmaxf(sh[t], sh[t + s]);
        __syncthreads();
    }
    const float cmx = sh[0];
    __syncthreads();
    const float e = expf(logit - cmx);
    sh[t] = e;
    __syncthreads();
    for (int s = 128; s; s >>= 1) {
        if (t < s) sh[t] += sh[t + s];
        __syncthreads();
    }
    const float csum = sh[0];
    __syncthreads();
    g_sqC[n * C_ + t] = sqrtf((float)C_ * e / csum);

    // ---- Phase B: spatial stats ----
    const float invCT = 1.0f / ((float)C_ * TEMP);
    const float4* rp = reinterpret_cast<const float4*>(g_rowsum + n * HW_);
    float mrs = -1e30f;
    for (int i = t; i < HW_ / 4; i += 256) {
        float4 a = rp[i];
        mrs = fmaxf(mrs, fmaxf(fmaxf(a.x, a.y), fmaxf(a.z, a.w)));
    }
    sh[t] = mrs;
    __syncthreads();
    for (int s = 128; s; s >>= 1) {
        if (t < s) sh[t] = fmaxf(sh[t], sh[t + s]);
        __syncthreads();
    }
    const float lmax = sh[0] * invCT;
    __syncthreads();

    float se = 0.0f;
    for (int i = t; i < HW_ / 4; i += 256) {
        float4 a = rp[i];
        se += expf(a.x * invCT - lmax) + expf(a.y * invCT - lmax)
            + expf(a.z * invCT - lmax) + expf(a.w * invCT - lmax);
    }
    sh[t] = se;
    __syncthreads();
    for (int s = 128; s; s >>= 1) {
        if (t < s) sh[t] += sh[t + s];
        __syncthreads();
    }
    __shared__ float sA;
    if (t == 0) {
        g_smax[n] = lmax;
        sA = sqrtf((float)HW_ / sh[0]);
        g_A[n] = sA;
    }
    __syncthreads();

    // ---- Phase C: masks ----
    __shared__ int   shmin[NB_], shmax[NB_], swmin[NB_], swmax[NB_];
    __shared__ float sarea[NB_];
    if (t < NB_) {
        const float* b = gt + (size_t)(n * NB_ + t) * 4;
        int wmin = (int)floorf(b[0] / IMGW * (float)W_);
        int wmax = (int)ceilf (b[2] / IMGW * (float)W_);
        int hmin = (int)floorf(b[1] / IMGH * (float)H_);
        int hmax = (int)ceilf (b[3] / IMGH * (float)H_);
        swmin[t] = wmin; swmax[t] = wmax; shmin[t] = hmin; shmax[t] = hmax;
        sarea[t] = 1.0f / (float)(hmax + 1 - hmin) / (float)(wmax + 1 - wmin);
    }
    __syncthreads();

    int cnt = 0;
    for (int i = t; i < HW_; i += 256) {
        const int hh = i >> 7;        // / W_
        const int ww = i & (W_ - 1);
        float fg = 0.0f;
#pragma unroll
        for (int b = 0; b < NB_; b++) {
            bool inside = (hh >= shmin[b]) & (hh <= shmax[b]) &
                          (ww >= swmin[b]) & (ww <= swmax[b]);
            if (inside) fg = fmaxf(fg, sarea[b]);
        }
        g_fg[n * HW_ + i] = fg;
        if (fg <= 0.0f) cnt++;
    }
    __shared__ int shi[256];
    shi[t] = cnt;
    __syncthreads();
    for (int s = 128; s; s >>= 1) {
        if (t < s) shi[t] += shi[t + s];
        __syncthreads();
    }
    __shared__ float sBg;
    if (t == 0) {
        int c = shi[0];
        sBg = sqrtf(1.0f / (float)(c > 0 ? c : 1));
    }
    __syncthreads();

    // ---- Phase D: per-row weights ----
    // w_row = sqrt(HW * softmax) * (sqrt(fg) + sqrt(bg))
    const float invCT2 = 0.5f * invCT;     // half-logit: sqrt(exp(x)) = exp(x/2)
    const float hlmax  = 0.5f * lmax;
    const float A = sA, Bg = sBg;
    for (int i = t; i < HW_; i += 256) {
        const float rs = g_rowsum[n * HW_ + i];
        const float fg = g_fg[n * HW_ + i];
        const float sqrtS = A * __expf(rs * invCT2 - hlmax);
        g_roww[n * HW_ + i] = sqrtS * (sqrtf(fg) + ((fg <= 0.0f) ? Bg : 0.0f));
    }
}

// ---------------------------------------------------------------------------
// K6: main pass over S and T — pure branchless streaming. Per-lane deferred
// reduction; last block finishes the scalar. Grid: K6_BLOCKS, 256 thr.
// ---------------------------------------------------------------------------
__global__ void __launch_bounds__(256) k6_main(const float* __restrict__ S,
                                              const float* __restrict__ T,
                                              float* __restrict__ out) {
    __shared__ float sqc[N_ * C_];
    for (int i = threadIdx.x; i < N_ * C_; i += 256) sqc[i] = g_sqC[i];
    __syncthreads();

    const int w = threadIdx.x >> 5;
    const int l = threadIdx.x & 31;
    const int gw = blockIdx.x * 8 + w;
    const int NW = K6_BLOCKS * 8;

    float acc = 0.0f;
#pragma unroll 4
    for (int r = gw; r < N_ * HW_; r += NW) {
        const int n = r & (N_ - 1);
        const int hw = r >> 3;
        // all 5 global loads issued up front (independent, front-batched)
        const float wrow = g_roww[n * HW_ + hw];   // warp-uniform broadcast
        const float4* ps = reinterpret_cast<const float4*>(S + (size_t)r * C_);
        const float4* pt = reinterpret_cast<const float4*>(T + (size_t)r * C_);
        float4 a = ps[l],      b = pt[l];
        float4 c = ps[32 + l], d = pt[32 + l];
        const float4* qr = reinterpret_cast<const float4*>(sqc + n * C_);
        float4 qa = qr[l], qb = qr[32 + l];

        float v = fabsf(a.x - b.x) * qa.x + fabsf(a.y - b.y) * qa.y
                + fabsf(a.z - b.z) * qa.z + fabsf(a.w - b.w) * qa.w
                + fabsf(c.x - d.x) * qb.x + fabsf(c.y - d.y) * qb.y
                + fabsf(c.z - d.z) * qb.z + fabsf(c.w - d.w) * qb.w;

        acc += v * wrow;             // deferred: no per-row shuffle chain
    }

#pragma unroll
    for (int off = 16; off; off >>= 1)
        acc += __shfl_xor_sync(0xffffffffu, acc, off);

    __shared__ float sp[8];
    if (l == 0) sp[w] = acc;
    __syncthreads();

    __shared__ bool is_last;
    if (threadIdx.x == 0) {
        float s = 0.0f;
#pragma unroll
        for (int i = 0; i < 8; i++) s += sp[i];
        g_part[blockIdx.x] = s;
        __threadfence();
        unsigned int prev = atomicAdd(&g_cnt, 1u);
        is_last = (prev == (unsigned)(K6_BLOCKS - 1));
    }
    __syncthreads();

    if (is_last) {
        // deterministic fixed-order final reduce over g_part
        __shared__ float sh[256];
        const int t = threadIdx.x;
        float s = 0.0f;
        for (int i = t; i < K6_BLOCKS; i += 256) s += g_part[i];
        sh[t] = s;
        __syncthreads();
        for (int st = 128; st; st >>= 1) {
            if (t < st) sh[t] += sh[t + st];
            __syncthreads();
        }
        if (t == 0) {
            out[0] = sh[0] / (float)HW_;   // RATIO == 1
            g_cnt = 0;                     // reset for next graph replay
        }
    }
}

extern "C" void kernel_launch(void* const* d_in, const int* in_sizes, int n_in,
                              void* d_out, int out_size) {
    const float* preds_S = (const float*)d_in[0];
    const float* preds_T = (const float*)d_in[1];
    const float* gt      = (const float*)d_in[2];
    float* out = (float*)d_out;

    k1_stats<<<dim3(K1_CHUNKS, N_), 256>>>(preds_T);
    kmeta<<<N_, 256>>>(gt);
    k6_main<<<K6_BLOCKS, 256>>>(preds_S, preds_T, out);
}

// round 12
// speedup vs baseline: 1.0919x; 1.0531x over previous
#include <cuda_runtime.h>

// Problem constants
#define N_   8
#define C_   256
#define H_   128
#define W_   128
#define HW_  16384
#define NB_  20
#define TEMP 0.5f
#define IMGW 800.0f
#define IMGH 800.0f

#define K1_CHUNKS 128                // hw chunks per image in K1 (128 rows each)
#define K1_BLOCKS (N_ * K1_CHUNKS)   // 1024
#define K6_BLOCKS 1024
#define KM_THREADS 1024

// Scratch (no allocation allowed -> __device__ globals)
__device__ float g_rowsum[N_ * HW_];          // sum_c |T|, indexed [n*HW + hw]
__device__ float g_colpart[K1_BLOCKS * C_];   // per-block partial channel sums
__device__ float g_sqC[N_ * C_];              // sqrt(C_att)
__device__ float g_fg[N_ * HW_];              // fg mask, [n*HW + hw]
__device__ float g_roww[N_ * HW_];            // per-row weight, [n*HW + hw]
__device__ float g_part[K6_BLOCKS];           // main-pass block partials
__device__ unsigned int g_cnt = 0;            // last-block counter (self-resetting)

// ---------------------------------------------------------------------------
// K1: one pass over preds_T. Row sums of |T| + partial channel sums.
// Grid: (K1_CHUNKS, N_) = 1024 blocks, 256 threads (8 warps).
// Each block: 128 rows; each warp: 16 rows strided by 8.
// ---------------------------------------------------------------------------
__global__ void __launch_bounds__(256) k1_stats(const float* __restrict__ T) {
    const int n = blockIdx.y;
    const int chunk = blockIdx.x;
    const int w = threadIdx.x >> 5;
    const int l = threadIdx.x & 31;

    __shared__ float scol[8][C_];

    float col[8];
#pragma unroll
    for (int j = 0; j < 8; j++) col[j] = 0.0f;

    const int hw0 = chunk * (HW_ / K1_CHUNKS);   // 128 rows per block
#pragma unroll 4
    for (int i = 0; i < 16; i++) {
        const int hw = hw0 + w + 8 * i;
        const float4* p = reinterpret_cast<const float4*>(T + (size_t)(hw * N_ + n) * C_);
        float4 a = p[l];        // c = 4l .. 4l+3
        float4 b = p[32 + l];   // c = 128+4l ..
        float a0 = fabsf(a.x), a1 = fabsf(a.y), a2 = fabsf(a.z), a3 = fabsf(a.w);
        float b0 = fabsf(b.x), b1 = fabsf(b.y), b2 = fabsf(b.z), b3 = fabsf(b.w);
        col[0] += a0; col[1] += a1; col[2] += a2; col[3] += a3;
        col[4] += b0; col[5] += b1; col[6] += b2; col[7] += b3;
        float rs = (a0 + a1) + (a2 + a3) + (b0 + b1) + (b2 + b3);
#pragma unroll
        for (int off = 16; off; off >>= 1)
            rs += __shfl_xor_sync(0xffffffffu, rs, off);
        if (l == 0) g_rowsum[n * HW_ + hw] = rs;
    }

#pragma unroll
    for (int j = 0; j < 4; j++) {
        scol[w][4 * l + j]       = col[j];
        scol[w][128 + 4 * l + j] = col[4 + j];
    }
    __syncthreads();

    const int t = threadIdx.x;  // 256 threads == C_
    float p = 0.0f;
#pragma unroll
    for (int ww = 0; ww < 8; ww++) p += scol[ww][t];
    g_colpart[(n * K1_CHUNKS + chunk) * C_ + t] = p;
}

// ---------------------------------------------------------------------------
// KMETA: fused per-image metadata. Grid: N_ blocks, 1024 threads.
// Phase A: channel softmax -> g_sqC.
// Phase B: spatial softmax stats.
// Phase C: box masks -> g_fg, bg count.
// Phase D: per-row weight -> g_roww.
// 1024 threads (vs 256 before): 4x in-flight loads, 1/4 the iterations.
// ---------------------------------------------------------------------------
__global__ void __launch_bounds__(KM_THREADS) kmeta(const float* __restrict__ gt) {
    const int n = blockIdx.x;
    const int t = threadIdx.x;

    __shared__ float sh[KM_THREADS];
    __shared__ float pA[4][C_];

    // ---- Phase A: channel softmax. (c, q) splits the 128-chunk sum 4 ways ----
    {
        const int c = t & (C_ - 1);
        const int q = t >> 8;           // 0..3
        float v = 0.0f;
#pragma unroll 8
        for (int k = q; k < K1_CHUNKS; k += 4)
            v += g_colpart[(n * K1_CHUNKS + k) * C_ + c];
        pA[q][c] = v;
    }
    __syncthreads();

    float e = 0.0f;     // valid only for t < 256
    {
        const int c = t & (C_ - 1);
        float logit = 0.0f;
        if (t < C_) {
            logit = ((pA[0][c] + pA[1][c] + pA[2][c] + pA[3][c]) / (float)HW_) / TEMP;
            sh[t] = logit;
        }
        __syncthreads();
        for (int s = 128; s; s >>= 1) {
            if (t < s) sh[t] = fmaxf(sh[t], sh[t + s]);
            __syncthreads();
        }
        const float cmx = sh[0];
        __syncthreads();
        if (t < C_) {
            e = expf(logit - cmx);
            sh[t] = e;
        }
        __syncthreads();
        for (int s = 128; s; s >>= 1) {
            if (t < s) sh[t] += sh[t + s];
            __syncthreads();
        }
        const float csum = sh[0];
        __syncthreads();
        if (t < C_)
            g_sqC[n * C_ + t] = sqrtf((float)C_ * e / csum);
    }

    // ---- Phase B: spatial stats (max + sum of exp over 16384 rowsums) ----
    const float invCT = 1.0f / ((float)C_ * TEMP);
    const float4* rp = reinterpret_cast<const float4*>(g_rowsum + n * HW_);
    float mrs = -1e30f;
#pragma unroll
    for (int i = 0; i < 4; i++) {
        float4 a = rp[t + i * KM_THREADS];
        mrs = fmaxf(mrs, fmaxf(fmaxf(a.x, a.y), fmaxf(a.z, a.w)));
    }
    sh[t] = mrs;
    __syncthreads();
    for (int s = 512; s; s >>= 1) {
        if (t < s) sh[t] = fmaxf(sh[t], sh[t + s]);
        __syncthreads();
    }
    const float lmax = sh[0] * invCT;
    __syncthreads();

    float se = 0.0f;
#pragma unroll
    for (int i = 0; i < 4; i++) {
        float4 a = rp[t + i * KM_THREADS];
        se += __expf(a.x * invCT - lmax) + __expf(a.y * invCT - lmax)
            + __expf(a.z * invCT - lmax) + __expf(a.w * invCT - lmax);
    }
    sh[t] = se;
    __syncthreads();
    for (int s = 512; s; s >>= 1) {
        if (t < s) sh[t] += sh[t + s];
        __syncthreads();
    }
    __shared__ float sA;
    if (t == 0) sA = sqrtf((float)HW_ / sh[0]);
    __syncthreads();

    // ---- Phase C: masks ----
    __shared__ int   shmin[NB_], shmax[NB_], swmin[NB_], swmax[NB_];
    __shared__ float sarea[NB_];
    if (t < NB_) {
        const float* b = gt + (size_t)(n * NB_ + t) * 4;
        int wmin = (int)floorf(b[0] / IMGW * (float)W_);
        int wmax = (int)ceilf (b[2] / IMGW * (float)W_);
        int hmin = (int)floorf(b[1] / IMGH * (float)H_);
        int hmax = (int)ceilf (b[3] / IMGH * (float)H_);
        swmin[t] = wmin; swmax[t] = wmax; shmin[t] = hmin; shmax[t] = hmax;
        sarea[t] = 1.0f / (float)(hmax + 1 - hmin) / (float)(wmax + 1 - wmin);
    }
    __syncthreads();

    int cnt = 0;
#pragma unroll 4
    for (int i = t; i < HW_; i += KM_THREADS) {
        const int hh = i >> 7;        // / W_
        const int ww = i & (W_ - 1);
        float fg = 0.0f;
#pragma unroll
        for (int b = 0; b < NB_; b++) {
            bool inside = (hh >= shmin[b]) & (hh <= shmax[b]) &
                          (ww >= swmin[b]) & (ww <= swmax[b]);
            if (inside) fg = fmaxf(fg, sarea[b]);
        }
        g_fg[n * HW_ + i] = fg;
        if (fg <= 0.0f) cnt++;
    }
    __shared__ int shi[KM_THREADS];
    shi[t] = cnt;
    __syncthreads();
    for (int s = 512; s; s >>= 1) {
        if (t < s) shi[t] += shi[t + s];
        __syncthreads();
    }
    __shared__ float sBg;
    if (t == 0) {
        int c = shi[0];
        sBg = sqrtf(1.0f / (float)(c > 0 ? c : 1));
    }
    __syncthreads();

    // ---- Phase D: per-row weights ----
    // w_row = sqrt(HW * softmax) * (sqrt(fg) + sqrt(bg))
    const float invCT2 = 0.5f * invCT;     // half-logit: sqrt(exp(x)) = exp(x/2)
    const float hlmax  = 0.5f * lmax;
    const float A = sA, Bg = sBg;
#pragma unroll 4
    for (int i = t; i < HW_; i += KM_THREADS) {
        const float rs = g_rowsum[n * HW_ + i];
        const float fg = g_fg[n * HW_ + i];
        const float sqrtS = A * __expf(rs * invCT2 - hlmax);
        g_roww[n * HW_ + i] = sqrtS * (sqrtf(fg) + ((fg <= 0.0f) ? Bg : 0.0f));
    }
}

// ---------------------------------------------------------------------------
// K6: main pass over S and T — lean streaming loop.
// n = r & 7 is warp-invariant (stride 8192 ≡ 0 mod 8) so the sqc row is
// hoisted out of the loop, and all pointers advance by constants.
// Grid: K6_BLOCKS, 256 thr.
// ---------------------------------------------------------------------------
__global__ void __launch_bounds__(256) k6_main(const float* __restrict__ S,
                                              const float* __restrict__ T,
                                              float* __restrict__ out) {
    __shared__ float sqc[N_ * C_];
    for (int i = threadIdx.x; i < N_ * C_; i += 256) sqc[i] = g_sqC[i];
    __syncthreads();

    const int w = threadIdx.x >> 5;
    const int l = threadIdx.x & 31;
    const int r0 = blockIdx.x * 8 + w;        // starting row for this warp
    const int n  = r0 & (N_ - 1);             // warp-invariant
    const int hw0 = r0 >> 3;

    // hoisted channel weights (loop-invariant)
    const float4* qr = reinterpret_cast<const float4*>(sqc + n * C_);
    const float4 qa = qr[l], qb = qr[32 + l];

    // pointers advance by compile-time constants
    const float4* ps = reinterpret_cast<const float4*>(S) + (size_t)r0 * (C_ / 4) + l;
    const float4* pt = reinterpret_cast<const float4*>(T) + (size_t)r0 * (C_ / 4) + l;
    const float*  pw = g_roww + n * HW_ + hw0;
    const int ROW_STRIDE4 = (K6_BLOCKS * 8) * (C_ / 4);   // float4 stride per iter
    const int W_STRIDE    = (K6_BLOCKS * 8) / N_;         // 1024

    float acc = 0.0f;
#pragma unroll 4
    for (int k = 0; k < (N_ * HW_) / (K6_BLOCKS * 8); k++) {   // 16 iters
        const float wrow = pw[0];               // warp-uniform broadcast
        float4 a = ps[0], c = ps[32];
        float4 b = pt[0], d = pt[32];

        float v = fabsf(a.x - b.x) * qa.x + fabsf(a.y - b.y) * qa.y
                + fabsf(a.z - b.z) * qa.z + fabsf(a.w - b.w) * qa.w
                + fabsf(c.x - d.x) * qb.x + fabsf(c.y - d.y) * qb.y
                + fabsf(c.z - d.z) * qb.z + fabsf(c.w - d.w) * qb.w;

        acc += v * wrow;
        ps += ROW_STRIDE4; pt += ROW_STRIDE4; pw += W_STRIDE;
    }

#pragma unroll
    for (int off = 16; off; off >>= 1)
        acc += __shfl_xor_sync(0xffffffffu, acc, off);

    __shared__ float sp[8];
    if (l == 0) sp[w] = acc;
    __syncthreads();

    __shared__ bool is_last;
    if (threadIdx.x == 0) {
        float s = 0.0f;
#pragma unroll
        for (int i = 0; i < 8; i++) s += sp[i];
        g_part[blockIdx.x] = s;
        __threadfence();
        unsigned int prev = atomicAdd(&g_cnt, 1u);
        is_last = (prev == (unsigned)(K6_BLOCKS - 1));
    }
    __syncthreads();

    if (is_last) {
        // deterministic fixed-order final reduce over g_part
        __shared__ float sh[256];
        const int t = threadIdx.x;
        float s = 0.0f;
        for (int i = t; i < K6_BLOCKS; i += 256) s += g_part[i];
        sh[t] = s;
        __syncthreads();
        for (int st = 128; st; st >>= 1) {
            if (t < st) sh[t] += sh[t + st];
            __syncthreads();
        }
        if (t == 0) {
            out[0] = sh[0] / (float)HW_;   // RATIO == 1
            g_cnt = 0;                     // reset for next graph replay
        }
    }
}

extern "C" void kernel_launch(void* const* d_in, const int* in_sizes, int n_in,
                              void* d_out, int out_size) {
    const float* preds_S = (const float*)d_in[0];
    const float* preds_T = (const float*)d_in[1];
    const float* gt      = (const float*)d_in[2];
    float* out = (float*)d_out;

    k1_stats<<<dim3(K1_CHUNKS, N_), 256>>>(preds_T);
    kmeta<<<N_, KM_THREADS>>>(gt);
    k6_main<<<K6_BLOCKS, 256>>>(preds_S, preds_T, out);
}

// round 13
// speedup vs baseline: 1.1513x; 1.0544x over previous
#include <cuda_runtime.h>

// Problem constants
#define N_   8
#define C_   256
#define H_   128
#define W_   128
#define HW_  16384
#define NB_  20
#define TEMP 0.5f
#define IMGW 800.0f
#define IMGH 800.0f

#define K1_CHUNKS 128                // hw chunks per image in K1 (128 rows each)
#define K1_BLOCKS (N_ * K1_CHUNKS)   // 1024
#define K6_BLOCKS 1024               // 128 consecutive rows per block
#define KM_THREADS 1024

// Scratch (no allocation allowed -> __device__ globals)
__device__ float g_rowsum[N_ * HW_];          // sum_c |T|, indexed [n*HW + hw]
__device__ float g_colpart[K1_BLOCKS * C_];   // per-block partial channel sums
__device__ float g_sqC[N_ * C_];              // sqrt(C_att)
__device__ float g_fg[N_ * HW_];              // fg mask, [n*HW + hw]
__device__ float g_roww[N_ * HW_];            // per-row weight, [n*HW + hw]
__device__ float g_part[K6_BLOCKS];           // main-pass block partials
__device__ unsigned int g_cnt = 0;            // last-block counter (self-resetting)

// ---------------------------------------------------------------------------
// K1: one pass over preds_T. Row sums of |T| + partial channel sums.
// Grid: (K1_CHUNKS, N_) = 1024 blocks, 256 threads (8 warps).
// Each block: 128 consecutive rows (128 KB window); warp w: rows w + 8i.
// ---------------------------------------------------------------------------
__global__ void __launch_bounds__(256) k1_stats(const float* __restrict__ T) {
    const int n = blockIdx.y;
    const int chunk = blockIdx.x;
    const int w = threadIdx.x >> 5;
    const int l = threadIdx.x & 31;

    __shared__ float scol[8][C_];

    float col[8];
#pragma unroll
    for (int j = 0; j < 8; j++) col[j] = 0.0f;

    const int hw0 = chunk * (HW_ / K1_CHUNKS);   // 128 rows per block
#pragma unroll 4
    for (int i = 0; i < 16; i++) {
        const int hw = hw0 + w + 8 * i;
        const float4* p = reinterpret_cast<const float4*>(T + (size_t)(hw * N_ + n) * C_);
        float4 a = p[l];        // c = 4l .. 4l+3
        float4 b = p[32 + l];   // c = 128+4l ..
        float a0 = fabsf(a.x), a1 = fabsf(a.y), a2 = fabsf(a.z), a3 = fabsf(a.w);
        float b0 = fabsf(b.x), b1 = fabsf(b.y), b2 = fabsf(b.z), b3 = fabsf(b.w);
        col[0] += a0; col[1] += a1; col[2] += a2; col[3] += a3;
        col[4] += b0; col[5] += b1; col[6] += b2; col[7] += b3;
        float rs = (a0 + a1) + (a2 + a3) + (b0 + b1) + (b2 + b3);
#pragma unroll
        for (int off = 16; off; off >>= 1)
            rs += __shfl_xor_sync(0xffffffffu, rs, off);
        if (l == 0) g_rowsum[n * HW_ + hw] = rs;
    }

#pragma unroll
    for (int j = 0; j < 4; j++) {
        scol[w][4 * l + j]       = col[j];
        scol[w][128 + 4 * l + j] = col[4 + j];
    }
    __syncthreads();

    const int t = threadIdx.x;  // 256 threads == C_
    float p = 0.0f;
#pragma unroll
    for (int ww = 0; ww < 8; ww++) p += scol[ww][t];
    g_colpart[(n * K1_CHUNKS + chunk) * C_ + t] = p;
}

// ---------------------------------------------------------------------------
// KMETA: fused per-image metadata. Grid: N_ blocks, 1024 threads.
// Phase A: channel softmax -> g_sqC.
// Phase B: spatial softmax stats.
// Phase C: box masks -> g_fg, bg count.
// Phase D: per-row weight -> g_roww.
// ---------------------------------------------------------------------------
__global__ void __launch_bounds__(KM_THREADS) kmeta(const float* __restrict__ gt) {
    const int n = blockIdx.x;
    const int t = threadIdx.x;

    __shared__ float sh[KM_THREADS];
    __shared__ float pA[4][C_];

    // ---- Phase A: channel softmax. (c, q) splits the 128-chunk sum 4 ways ----
    {
        const int c = t & (C_ - 1);
        const int q = t >> 8;           // 0..3
        float v = 0.0f;
#pragma unroll 8
        for (int k = q; k < K1_CHUNKS; k += 4)
            v += g_colpart[(n * K1_CHUNKS + k) * C_ + c];
        pA[q][c] = v;
    }
    __syncthreads();

    float e = 0.0f;     // valid only for t < 256
    {
        const int c = t & (C_ - 1);
        float logit = 0.0f;
        if (t < C_) {
            logit = ((pA[0][c] + pA[1][c] + pA[2][c] + pA[3][c]) / (float)HW_) / TEMP;
            sh[t] = logit;
        }
        __syncthreads();
        for (int s = 128; s; s >>= 1) {
            if (t < s) sh[t] = fmaxf(sh[t], sh[t + s]);
            __syncthreads();
        }
        const float cmx = sh[0];
        __syncthreads();
        if (t < C_) {
            e = expf(logit - cmx);
            sh[t] = e;
        }
        __syncthreads();
        for (int s = 128; s; s >>= 1) {
            if (t < s) sh[t] += sh[t + s];
            __syncthreads();
        }
        const float csum = sh[0];
        __syncthreads();
        if (t < C_)
            g_sqC[n * C_ + t] = sqrtf((float)C_ * e / csum);
    }

    // ---- Phase B: spatial stats (max + sum of exp over 16384 rowsums) ----
    const float invCT = 1.0f / ((float)C_ * TEMP);
    const float4* rp = reinterpret_cast<const float4*>(g_rowsum + n * HW_);
    float mrs = -1e30f;
#pragma unroll
    for (int i = 0; i < 4; i++) {
        float4 a = rp[t + i * KM_THREADS];
        mrs = fmaxf(mrs, fmaxf(fmaxf(a.x, a.y), fmaxf(a.z, a.w)));
    }
    sh[t] = mrs;
    __syncthreads();
    for (int s = 512; s; s >>= 1) {
        if (t < s) sh[t] = fmaxf(sh[t], sh[t + s]);
        __syncthreads();
    }
    const float lmax = sh[0] * invCT;
    __syncthreads();

    float se = 0.0f;
#pragma unroll
    for (int i = 0; i < 4; i++) {
        float4 a = rp[t + i * KM_THREADS];
        se += __expf(a.x * invCT - lmax) + __expf(a.y * invCT - lmax)
            + __expf(a.z * invCT - lmax) + __expf(a.w * invCT - lmax);
    }
    sh[t] = se;
    __syncthreads();
    for (int s = 512; s; s >>= 1) {
        if (t < s) sh[t] += sh[t + s];
        __syncthreads();
    }
    __shared__ float sA;
    if (t == 0) sA = sqrtf((float)HW_ / sh[0]);
    __syncthreads();

    // ---- Phase C: masks ----
    __shared__ int   shmin[NB_], shmax[NB_], swmin[NB_], swmax[NB_];
    __shared__ float sarea[NB_];
    if (t < NB_) {
        const float* b = gt + (size_t)(n * NB_ + t) * 4;
        int wmin = (int)floorf(b[0] / IMGW * (float)W_);
        int wmax = (int)ceilf (b[2] / IMGW * (float)W_);
        int hmin = (int)floorf(b[1] / IMGH * (float)H_);
        int hmax = (int)ceilf (b[3] / IMGH * (float)H_);
        swmin[t] = wmin; swmax[t] = wmax; shmin[t] = hmin; shmax[t] = hmax;
        sarea[t] = 1.0f / (float)(hmax + 1 - hmin) / (float)(wmax + 1 - wmin);
    }
    __syncthreads();

    int cnt = 0;
#pragma unroll 4
    for (int i = t; i < HW_; i += KM_THREADS) {
        const int hh = i >> 7;        // / W_
        const int ww = i & (W_ - 1);
        float fg = 0.0f;
#pragma unroll
        for (int b = 0; b < NB_; b++) {
            bool inside = (hh >= shmin[b]) & (hh <= shmax[b]) &
                          (ww >= swmin[b]) & (ww <= swmax[b]);
            if (inside) fg = fmaxf(fg, sarea[b]);
        }
        g_fg[n * HW_ + i] = fg;
        if (fg <= 0.0f) cnt++;
    }
    __shared__ int shi[KM_THREADS];
    shi[t] = cnt;
    __syncthreads();
    for (int s = 512; s; s >>= 1) {
        if (t < s) shi[t] += shi[t + s];
        __syncthreads();
    }
    __shared__ float sBg;
    if (t == 0) {
        int c = shi[0];
        sBg = sqrtf(1.0f / (float)(c > 0 ? c : 1));
    }
    __syncthreads();

    // ---- Phase D: per-row weights ----
    // w_row = sqrt(HW * softmax) * (sqrt(fg) + sqrt(bg))
    const float invCT2 = 0.5f * invCT;     // half-logit: sqrt(exp(x)) = exp(x/2)
    const float hlmax  = 0.5f * lmax;
    const float A = sA, Bg = sBg;
#pragma unroll 4
    for (int i = t; i < HW_; i += KM_THREADS) {
        const float rs = g_rowsum[n * HW_ + i];
        const float fg = g_fg[n * HW_ + i];
        const float sqrtS = A * __expf(rs * invCT2 - hlmax);
        g_roww[n * HW_ + i] = sqrtS * (sqrtf(fg) + ((fg <= 0.0f) ? Bg : 0.0f));
    }
}

// ---------------------------------------------------------------------------
// K6: main pass over S and T — contiguous 128 KB window per block.
// Block b owns rows [b*128, b*128+128); warp w takes rows b*128 + 8k + w,
// so n = w is warp-invariant (sqc row hoisted), iteration stride is 8 KB
// inside the block's window, and g_roww reads are sequential.
// S is read with __ldcs (read-once, evict-first); T default (may hit L2
// residue from k1). Grid: K6_BLOCKS, 256 thr.
// ---------------------------------------------------------------------------
__global__ void __launch_bounds__(256) k6_main(const float* __restrict__ S,
                                              const float* __restrict__ T,
                                              float* __restrict__ out) {
    __shared__ float sqc[N_ * C_];
    for (int i = threadIdx.x; i < N_ * C_; i += 256) sqc[i] = g_sqC[i];
    __syncthreads();

    const int w = threadIdx.x >> 5;           // == n for this warp
    const int l = threadIdx.x & 31;
    const int base = blockIdx.x * 128;        // first row of this block

    // hoisted channel weights (n == w, loop-invariant)
    const float4* qr = reinterpret_cast<const float4*>(sqc + w * C_);
    const float4 qa = qr[l], qb = qr[32 + l];

    // row r = base + 8k + w;  hw = base/8 + k
    const float4* ps = reinterpret_cast<const float4*>(S) + (size_t)(base + w) * (C_ / 4) + l;
    const float4* pt = reinterpret_cast<const float4*>(T) + (size_t)(base + w) * (C_ / 4) + l;
    const float*  pw = g_roww + w * HW_ + (base >> 3);
    const int STRIDE4 = 8 * (C_ / 4);         // 8 rows per iteration step

    float acc = 0.0f;
#pragma unroll 4
    for (int k = 0; k < 16; k++) {
        const float wrow = pw[k];             // warp-uniform, sequential
        float4 a = __ldcs(ps);                // S: read-once, evict-first
        float4 c = __ldcs(ps + 32);
        float4 b = pt[0];                     // T: default policy
        float4 d = pt[32];

        float v = fabsf(a.x - b.x) * qa.x + fabsf(a.y - b.y) * qa.y
                + fabsf(a.z - b.z) * qa.z + fabsf(a.w - b.w) * qa.w
                + fabsf(c.x - d.x) * qb.x + fabsf(c.y - d.y) * qb.y
                + fabsf(c.z - d.z) * qb.z + fabsf(c.w - d.w) * qb.w;

        acc += v * wrow;
        ps += STRIDE4; pt += STRIDE4;
    }

#pragma unroll
    for (int off = 16; off; off >>= 1)
        acc += __shfl_xor_sync(0xffffffffu, acc, off);

    __shared__ float sp[8];
    if (l == 0) sp[w] = acc;
    __syncthreads();

    __shared__ bool is_last;
    if (threadIdx.x == 0) {
        float s = 0.0f;
#pragma unroll
        for (int i = 0; i < 8; i++) s += sp[i];
        g_part[blockIdx.x] = s;
        __threadfence();
        unsigned int prev = atomicAdd(&g_cnt, 1u);
        is_last = (prev == (unsigned)(K6_BLOCKS - 1));
    }
    __syncthreads();

    if (is_last) {
        // deterministic fixed-order final reduce over g_part
        __shared__ float sh[256];
        const int t = threadIdx.x;
        float s = 0.0f;
        for (int i = t; i < K6_BLOCKS; i += 256) s += g_part[i];
        sh[t] = s;
        __syncthreads();
        for (int st = 128; st; st >>= 1) {
            if (t < st) sh[t] += sh[t + st];
            __syncthreads();
        }
        if (t == 0) {
            out[0] = sh[0] / (float)HW_;   // RATIO == 1
            g_cnt = 0;                     // reset for next graph replay
        }
    }
}

extern "C" void kernel_launch(void* const* d_in, const int* in_sizes, int n_in,
                              void* d_out, int out_size) {
    const float* preds_S = (const float*)d_in[0];
    const float* preds_T = (const float*)d_in[1];
    const float* gt      = (const float*)d_in[2];
    float* out = (float*)d_out;

    k1_stats<<<dim3(K1_CHUNKS, N_), 256>>>(preds_T);
    kmeta<<<N_, KM_THREADS>>>(gt);
    k6_main<<<K6_BLOCKS, 256>>>(preds_S, preds_T, out);
}

// round 15
// speedup vs baseline: 1.2167x; 1.0568x over previous
#include <cuda_runtime.h>
#include <cstdint>

// Problem constants
#define N_   8
#define C_   256
#define H_   128
#define W_   128
#define HW_  16384
#define NB_  20
#define TEMP 0.5f
#define IMGW 800.0f
#define IMGH 800.0f

#define K1_CHUNKS 128                // hw chunks per image in K1 (128 rows each)
#define K1_BLOCKS (N_ * K1_CHUNKS)   // 1024
#define K6_BLOCKS 1024               // 128 consecutive rows per block
#define KM_THREADS 1024

// Scratch (no allocation allowed -> __device__ globals)
__device__ float g_rowsum[N_ * HW_];          // sum_c |T|, indexed [n*HW + hw]
__device__ float g_colpart[K1_BLOCKS * C_];   // per-block partial channel sums
__device__ float g_sqC[N_ * C_];              // sqrt(C_att)
__device__ float g_fg[N_ * HW_];              // fg mask, [n*HW + hw]
__device__ float g_roww[N_ * HW_];            // per-row weight, [n*HW + hw]
__device__ float g_part[K6_BLOCKS];           // main-pass block partials
__device__ unsigned int g_cnt = 0;            // last-block counter (self-resetting)

// ---- L2 cache-hint policy helpers (sm_80+) ----------------------------------
__device__ __forceinline__ uint64_t policy_evict_last() {
    uint64_t pol;
    asm("createpolicy.fractional.L2::evict_last.b64 %0, 1.0;" : "=l"(pol));
    return pol;
}
__device__ __forceinline__ uint64_t policy_evict_first() {
    uint64_t pol;
    asm("createpolicy.fractional.L2::evict_first.b64 %0, 1.0;" : "=l"(pol));
    return pol;
}
__device__ __forceinline__ float4 ld_pol(const float4* p, uint64_t pol) {
    float4 v;
    asm volatile("ld.global.L2::cache_hint.v4.f32 {%0,%1,%2,%3}, [%4], %5;"
                 : "=f"(v.x), "=f"(v.y), "=f"(v.z), "=f"(v.w)
                 : "l"(p), "l"(pol));
    return v;
}

// ---------------------------------------------------------------------------
// K1: one pass over preds_T. Row sums of |T| + partial channel sums.
// T lines are loaded with L2 evict_last policy so they REMAIN in L2 (126 MB
// vs T = 128 MB) for k6's second read of T.
// Grid: (K1_CHUNKS, N_) = 1024 blocks, 256 threads (8 warps).
// ---------------------------------------------------------------------------
__global__ void __launch_bounds__(256) k1_stats(const float* __restrict__ T) {
    const int n = blockIdx.y;
    const int chunk = blockIdx.x;
    const int w = threadIdx.x >> 5;
    const int l = threadIdx.x & 31;

    __shared__ float scol[8][C_];

    const uint64_t pol = policy_evict_last();

    float col[8];
#pragma unroll
    for (int j = 0; j < 8; j++) col[j] = 0.0f;

    const int hw0 = chunk * (HW_ / K1_CHUNKS);   // 128 rows per block
#pragma unroll 4
    for (int i = 0; i < 16; i++) {
        const int hw = hw0 + w + 8 * i;
        const float4* p = reinterpret_cast<const float4*>(T + (size_t)(hw * N_ + n) * C_);
        float4 a = ld_pol(p + l, pol);        // c = 4l .. 4l+3  (protected in L2)
        float4 b = ld_pol(p + 32 + l, pol);   // c = 128+4l ..
        float a0 = fabsf(a.x), a1 = fabsf(a.y), a2 = fabsf(a.z), a3 = fabsf(a.w);
        float b0 = fabsf(b.x), b1 = fabsf(b.y), b2 = fabsf(b.z), b3 = fabsf(b.w);
        col[0] += a0; col[1] += a1; col[2] += a2; col[3] += a3;
        col[4] += b0; col[5] += b1; col[6] += b2; col[7] += b3;
        float rs = (a0 + a1) + (a2 + a3) + (b0 + b1) + (b2 + b3);
#pragma unroll
        for (int off = 16; off; off >>= 1)
            rs += __shfl_xor_sync(0xffffffffu, rs, off);
        if (l == 0) g_rowsum[n * HW_ + hw] = rs;
    }

#pragma unroll
    for (int j = 0; j < 4; j++) {
        scol[w][4 * l + j]       = col[j];
        scol[w][128 + 4 * l + j] = col[4 + j];
    }
    __syncthreads();

    const int t = threadIdx.x;  // 256 threads == C_
    float p = 0.0f;
#pragma unroll
    for (int ww = 0; ww < 8; ww++) p += scol[ww][t];
    g_colpart[(n * K1_CHUNKS + chunk) * C_ + t] = p;
}

// ---------------------------------------------------------------------------
// KMETA: fused per-image metadata. Grid: N_ blocks, 1024 threads.
// Phase A: channel softmax -> g_sqC.
// Phase B: spatial softmax stats.
// Phase C: box masks -> g_fg, bg count.
// Phase D: per-row weight -> g_roww.
// ---------------------------------------------------------------------------
__global__ void __launch_bounds__(KM_THREADS) kmeta(const float* __restrict__ gt) {
    const int n = blockIdx.x;
    const int t = threadIdx.x;

    __shared__ float sh[KM_THREADS];
    __shared__ float pA[4][C_];

    // ---- Phase A: channel softmax. (c, q) splits the 128-chunk sum 4 ways ----
    {
        const int c = t & (C_ - 1);
        const int q = t >> 8;           // 0..3
        float v = 0.0f;
#pragma unroll 8
        for (int k = q; k < K1_CHUNKS; k += 4)
            v += g_colpart[(n * K1_CHUNKS + k) * C_ + c];
        pA[q][c] = v;
    }
    __syncthreads();

    float e = 0.0f;     // valid only for t < 256
    {
        const int c = t & (C_ - 1);
        float logit = 0.0f;
        if (t < C_) {
            logit = ((pA[0][c] + pA[1][c] + pA[2][c] + pA[3][c]) / (float)HW_) / TEMP;
            sh[t] = logit;
        }
        __syncthreads();
        for (int s = 128; s; s >>= 1) {
            if (t < s) sh[t] = fmaxf(sh[t], sh[t + s]);
            __syncthreads();
        }
        const float cmx = sh[0];
        __syncthreads();
        if (t < C_) {
            e = expf(logit - cmx);
            sh[t] = e;
        }
        __syncthreads();
        for (int s = 128; s; s >>= 1) {
            if (t < s) sh[t] += sh[t + s];
            __syncthreads();
        }
        const float csum = sh[0];
        __syncthreads();
        if (t < C_)
            g_sqC[n * C_ + t] = sqrtf((float)C_ * e / csum);
    }

    // ---- Phase B: spatial stats (max + sum of exp over 16384 rowsums) ----
    const float invCT = 1.0f / ((float)C_ * TEMP);
    const float4* rp = reinterpret_cast<const float4*>(g_rowsum + n * HW_);
    float mrs = -1e30f;
#pragma unroll
    for (int i = 0; i < 4; i++) {
        float4 a = rp[t + i * KM_THREADS];
        mrs = fmaxf(mrs, fmaxf(fmaxf(a.x, a.y), fmaxf(a.z, a.w)));
    }
    sh[t] = mrs;
    __syncthreads();
    for (int s = 512; s; s >>= 1) {
        if (t < s) sh[t] = fmaxf(sh[t], sh[t + s]);
        __syncthreads();
    }
    const float lmax = sh[0] * invCT;
    __syncthreads();

    float se = 0.0f;
#pragma unroll
    for (int i = 0; i < 4; i++) {
        float4 a = rp[t + i * KM_THREADS];
        se += __expf(a.x * invCT - lmax) + __expf(a.y * invCT - lmax)
            + __expf(a.z * invCT - lmax) + __expf(a.w * invCT - lmax);
    }
    sh[t] = se;
    __syncthreads();
    for (int s = 512; s; s >>= 1) {
        if (t < s) sh[t] += sh[t + s];
        __syncthreads();
    }
    __shared__ float sA;
    if (t == 0) sA = sqrtf((float)HW_ / sh[0]);
    __syncthreads();

    // ---- Phase C: masks ----
    __shared__ int   shmin[NB_], shmax[NB_], swmin[NB_], swmax[NB_];
    __shared__ float sarea[NB_];
    if (t < NB_) {
        const float* b = gt + (size_t)(n * NB_ + t) * 4;
        int wmin = (int)floorf(b[0] / IMGW * (float)W_);
        int wmax = (int)ceilf (b[2] / IMGW * (float)W_);
        int hmin = (int)floorf(b[1] / IMGH * (float)H_);
        int hmax = (int)ceilf (b[3] / IMGH * (float)H_);
        swmin[t] = wmin; swmax[t] = wmax; shmin[t] = hmin; shmax[t] = hmax;
        sarea[t] = 1.0f / (float)(hmax + 1 - hmin) / (float)(wmax + 1 - wmin);
    }
    __syncthreads();

    int cnt = 0;
#pragma unroll 4
    for (int i = t; i < HW_; i += KM_THREADS) {
        const int hh = i >> 7;        // / W_
        const int ww = i & (W_ - 1);
        float fg = 0.0f;
#pragma unroll
        for (int b = 0; b < NB_; b++) {
            bool inside = (hh >= shmin[b]) & (hh <= shmax[b]) &
                          (ww >= swmin[b]) & (ww <= swmax[b]);
            if (inside) fg = fmaxf(fg, sarea[b]);
        }
        g_fg[n * HW_ + i] = fg;
        if (fg <= 0.0f) cnt++;
    }
    __shared__ int shi[KM_THREADS];
    shi[t] = cnt;
    __syncthreads();
    for (int s = 512; s; s >>= 1) {
        if (t < s) shi[t] += shi[t + s];
        __syncthreads();
    }
    __shared__ float sBg;
    if (t == 0) {
        int c = shi[0];
        sBg = sqrtf(1.0f / (float)(c > 0 ? c : 1));
    }
    __syncthreads();

    // ---- Phase D: per-row weights ----
    // w_row = sqrt(HW * softmax) * (sqrt(fg) + sqrt(bg))
    const float invCT2 = 0.5f * invCT;     // half-logit: sqrt(exp(x)) = exp(x/2)
    const float hlmax  = 0.5f * lmax;
    const float A = sA, Bg = sBg;
#pragma unroll 4
    for (int i = t; i < HW_; i += KM_THREADS) {
        const float rs = g_rowsum[n * HW_ + i];
        const float fg = g_fg[n * HW_ + i];
        const float sqrtS = A * __expf(rs * invCT2 - hlmax);
        g_roww[n * HW_ + i] = sqrtS * (sqrtf(fg) + ((fg <= 0.0f) ? Bg : 0.0f));
    }
}

// ---------------------------------------------------------------------------
// K6: main pass over S and T — contiguous 128 KB window per block.
// Block b owns rows [b*128, b*128+128); warp w takes rows b*128 + 8k + w,
// so n = w is warp-invariant (sqc row hoisted), iteration stride is 8 KB
// inside the block's window, and g_roww reads are sequential.
// S and T are loaded with L2 evict_first policy: S is read-once streaming
// and must NOT displace the evict_last-protected T lines left by k1; T is
// demoted after its (single) read here, releasing capacity.
// Grid: K6_BLOCKS, 256 thr.
// ---------------------------------------------------------------------------
__global__ void __launch_bounds__(256) k6_main(const float* __restrict__ S,
                                              const float* __restrict__ T,
                                              float* __restrict__ out) {
    __shared__ float sqc[N_ * C_];
    for (int i = threadIdx.x; i < N_ * C_; i += 256) sqc[i] = g_sqC[i];
    __syncthreads();

    const int w = threadIdx.x >> 5;           // == n for this warp
    const int l = threadIdx.x & 31;
    const int base = blockIdx.x * 128;        // first row of this block

    const uint64_t pol = policy_evict_first();

    // hoisted channel weights (n == w, loop-invariant)
    const float4* qr = reinterpret_cast<const float4*>(sqc + w * C_);
    const float4 qa = qr[l], qb = qr[32 + l];

    // row r = base + 8k + w;  hw = base/8 + k
    const float4* ps = reinterpret_cast<const float4*>(S) + (size_t)(base + w) * (C_ / 4) + l;
    const float4* pt = reinterpret_cast<const float4*>(T) + (size_t)(base + w) * (C_ / 4) + l;
    const float*  pw = g_roww + w * HW_ + (base >> 3);
    const int STRIDE4 = 8 * (C_ / 4);         // 8 rows per iteration step

    float acc = 0.0f;
#pragma unroll 4
    for (int k = 0; k < 16; k++) {
        const float wrow = pw[k];             // warp-uniform, sequential
        float4 a = ld_pol(ps, pol);           // S: streaming, don't pollute L2
        float4 c = ld_pol(ps + 32, pol);
        float4 b = ld_pol(pt, pol);           // T: hit protected line, then demote
        float4 d = ld_pol(pt + 32, pol);

        float v = fabsf(a.x - b.x) * qa.x + fabsf(a.y - b.y) * qa.y
                + fabsf(a.z - b.z) * qa.z + fabsf(a.w - b.w) * qa.w
                + fabsf(c.x - d.x) * qb.x + fabsf(c.y - d.y) * qb.y
                + fabsf(c.z - d.z) * qb.z + fabsf(c.w - d.w) * qb.w;

        acc += v * wrow;
        ps += STRIDE4; pt += STRIDE4;
    }

#pragma unroll
    for (int off = 16; off; off >>= 1)
        acc += __shfl_xor_sync(0xffffffffu, acc, off);

    __shared__ float sp[8];
    if (l == 0) sp[w] = acc;
    __syncthreads();

    __shared__ bool is_last;
    if (threadIdx.x == 0) {
        float s = 0.0f;
#pragma unroll
        for (int i = 0; i < 8; i++) s += sp[i];
        g_part[blockIdx.x] = s;
        __threadfence();
        unsigned int prev = atomicAdd(&g_cnt, 1u);
        is_last = (prev == (unsigned)(K6_BLOCKS - 1));
    }
    __syncthreads();

    if (is_last) {
        // deterministic fixed-order final reduce over g_part
        __shared__ float sh[256];
        const int t = threadIdx.x;
        float s = 0.0f;
        for (int i = t; i < K6_BLOCKS; i += 256) s += g_part[i];
        sh[t] = s;
        __syncthreads();
        for (int st = 128; st; st >>= 1) {
            if (t < st) sh[t] += sh[t + st];
            __syncthreads();
        }
        if (t == 0) {
            out[0] = sh[0] / (float)HW_;   // RATIO == 1
            g_cnt = 0;                     // reset for next graph replay
        }
    }
}

extern "C" void kernel_launch(void* const* d_in, const int* in_sizes, int n_in,
                              void* d_out, int out_size) {
    const float* preds_S = (const float*)d_in[0];
    const float* preds_T = (const float*)d_in[1];
    const float* gt      = (const float*)d_in[2];
    float* out = (float*)d_out;

    k1_stats<<<dim3(K1_CHUNKS, N_), 256>>>(preds_T);
    kmeta<<<N_, KM_THREADS>>>(gt);
    k6_main<<<K6_BLOCKS, 256>>>(preds_S, preds_T, out);
}